// round 6
// baseline (speedup 1.0000x reference)
#include <cuda_runtime.h>
#include <cuda_bf16.h>
#include <cstdint>
#include <cstddef>

// ---------------------------------------------------------------------------
// Lfm2ShortConv (sm_103 legacy-tensor path; tcgen05 rejected by toolchain).
// R6: bf16 two-term split GEMMs. X = Xhi + Xlo (bf16 each);
//   A*B ~= Ahi*Bhi + Ahi*Blo + Alo*Bhi   (lo*lo dropped, ~2^-18 rel)
// mma.sync.m16n8k16.bf16 runs 2x the tf32 FLOP rate -> 0.75x GEMM time.
// Operands stored k-permuted per 32-block so each thread's fragment pairs
// {2c,2c+1,2c+8,2c+9,(+16)} are contiguous 16B -> LDS.128 per row per k32.
// ---------------------------------------------------------------------------

#define SEQ  4096
#define HD   2048
#define MTOT 8192
#define KD   2048
#define NN1  6144
#define NN2  2048

// Scratch (__device__ globals: allocation-free rule). u32 = packed bf16 pair.
__device__ uint32_t g_hid_hi [(size_t)MTOT * KD / 2];
__device__ uint32_t g_hid_lo [(size_t)MTOT * KD / 2];
__device__ uint32_t g_win_hi [(size_t)NN1  * KD / 2];
__device__ uint32_t g_win_lo [(size_t)NN1  * KD / 2];
__device__ uint32_t g_wout_hi[(size_t)NN2  * KD / 2];
__device__ uint32_t g_wout_lo[(size_t)NN2  * KD / 2];
__device__ uint32_t g_y_hi   [(size_t)MTOT * KD / 2];
__device__ uint32_t g_y_lo   [(size_t)MTOT * KD / 2];
__device__ float    g_BCx    [(size_t)MTOT * NN1];

// ---- GEMM tiling ----------------------------------------------------------
constexpr int BM = 128, BN = 256, BK = 32;
constexpr int NTHREADS = 256;                  // 8 warps: 2 (M) x 4 (N)
constexpr int WM_ = 64, WN_ = 64;
constexpr int MT = WM_ / 16;                   // 4
constexpr int NT = WN_ / 8;                    // 8
constexpr int STAGES = 3;
constexpr int ASTR = 40;                       // row stride in bf16 (80 B, 16B-mult)
constexpr int A_PLANE = BM * ASTR;             // 5120 bf16
constexpr int B_PLANE = BN * ASTR;             // 10240 bf16
constexpr int STAGE_U16 = 2 * A_PLANE + 2 * B_PLANE;   // 30720
constexpr int SMEM_BYTES = STAGES * STAGE_U16 * 2;     // 184320

// ---- PTX helpers ----------------------------------------------------------
__device__ __forceinline__ void cp_async16(void* smem_dst, const void* gsrc) {
    uint32_t saddr = (uint32_t)__cvta_generic_to_shared(smem_dst);
    asm volatile("cp.async.cg.shared.global [%0], [%1], 16;\n"
                 :: "r"(saddr), "l"(gsrc));
}
__device__ __forceinline__ void cp_commit() {
    asm volatile("cp.async.commit_group;\n");
}
template <int N>
__device__ __forceinline__ void cp_wait() {
    asm volatile("cp.async.wait_group %0;\n" :: "n"(N));
}
__device__ __forceinline__ void mma_bf16(float* c, const uint32_t* a, const uint32_t* b) {
    asm volatile(
        "mma.sync.aligned.m16n8k16.row.col.f32.bf16.bf16.f32 "
        "{%0,%1,%2,%3}, {%4,%5,%6,%7}, {%8,%9}, {%0,%1,%2,%3};\n"
        : "+f"(c[0]), "+f"(c[1]), "+f"(c[2]), "+f"(c[3])
        : "r"(a[0]), "r"(a[1]), "r"(a[2]), "r"(a[3]), "r"(b[0]), "r"(b[1]));
}
__device__ __forceinline__ uint16_t bf16_bits(float f) {
    __nv_bfloat16 b = __float2bfloat16_rn(f);
    return *reinterpret_cast<uint16_t*>(&b);
}
__device__ __forceinline__ float bf16_val(float f) {
    return __bfloat162float(__float2bfloat16_rn(f));
}

// ---- TN GEMM: C[M,N] = A[M,K] * B[N,K]^T  via bf16 split ------------------
// Ahi/Alo/Bhi/Blo are packed-pair (u32) views of k-permuted bf16 planes.
__global__ void __launch_bounds__(NTHREADS, 1)
gemm_bf16s_tn(const uint32_t* __restrict__ Ahi, const uint32_t* __restrict__ Alo,
              const uint32_t* __restrict__ Bhi, const uint32_t* __restrict__ Blo,
              float* __restrict__ C, int N, int K)
{
    extern __shared__ char smc[];
    uint16_t* sm16 = (uint16_t*)smc;

    const int tid  = threadIdx.x;
    const int lane = tid & 31;
    const int warp = tid >> 5;
    const int wm = (warp >> 2) * WM_;          // 0 or 64
    const int wn = (warp & 3)  * WN_;          // 0,64,128,192
    const int g  = lane >> 2;                  // 0..7
    const int c  = lane & 3;                   // 0..3

    const int brow = blockIdx.y * BM;
    const int bcol = blockIdx.x * BN;
    const int Ku = K / 2;                      // u32 row stride
    const uint32_t* Agh = Ahi + (size_t)brow * Ku;
    const uint32_t* Agl = Alo + (size_t)brow * Ku;
    const uint32_t* Bgh = Bhi + (size_t)bcol * Ku;
    const uint32_t* Bgl = Blo + (size_t)bcol * Ku;

    float acc[MT][NT][4];
    #pragma unroll
    for (int i = 0; i < MT; i++)
        #pragma unroll
        for (int j = 0; j < NT; j++)
            #pragma unroll
            for (int q = 0; q < 4; q++) acc[i][j][q] = 0.f;

    const int KT = K / BK;

    auto prefetch = [&](int kt, int st) {
        const int k0u = kt * (BK / 2);                   // u32 offset in row
        uint16_t* sA_hi = sm16 + st * STAGE_U16;
        uint16_t* sA_lo = sA_hi + A_PLANE;
        uint16_t* sB_hi = sA_lo + A_PLANE;
        uint16_t* sB_lo = sB_hi + B_PLANE;
        // A: 128 rows x 4 chunks x 2 planes
        #pragma unroll
        for (int i = 0; i < 2; i++) {
            int idx = tid + i * NTHREADS;                // 0..511
            int r = idx >> 2, cc = idx & 3;
            cp_async16(&sA_hi[r * ASTR + cc * 8], Agh + (size_t)r * Ku + k0u + cc * 4);
            cp_async16(&sA_lo[r * ASTR + cc * 8], Agl + (size_t)r * Ku + k0u + cc * 4);
        }
        // B: 256 rows x 4 chunks x 2 planes
        #pragma unroll
        for (int i = 0; i < 4; i++) {
            int idx = tid + i * NTHREADS;                // 0..1023
            int r = idx >> 2, cc = idx & 3;
            cp_async16(&sB_hi[r * ASTR + cc * 8], Bgh + (size_t)r * Ku + k0u + cc * 4);
            cp_async16(&sB_lo[r * ASTR + cc * 8], Bgl + (size_t)r * Ku + k0u + cc * 4);
        }
        cp_commit();
    };

    prefetch(0, 0);
    prefetch(1, 1);

    int st = 0;
    for (int kt = 0; kt < KT; ++kt) {
        cp_wait<1>();
        __syncthreads();
        if (kt + 2 < KT) prefetch(kt + 2, (st + 2) % 3);

        const uint16_t* sA_hi = sm16 + st * STAGE_U16;
        const uint16_t* sA_lo = sA_hi + A_PLANE;
        const uint16_t* sB_hi = sA_lo + A_PLANE;
        const uint16_t* sB_lo = sB_hi + B_PLANE;

        #pragma unroll
        for (int nh = 0; nh < 2; ++nh) {
            uint4 Bh[4], Bl[4];
            #pragma unroll
            for (int j = 0; j < 4; ++j) {
                int off = (wn + (nh * 4 + j) * 8 + g) * ASTR + c * 8;
                Bh[j] = *(const uint4*)(sB_hi + off);
                Bl[j] = *(const uint4*)(sB_lo + off);
            }
            #pragma unroll
            for (int mi = 0; mi < MT; ++mi) {
                const int r0 = wm + mi * 16 + g;
                const int o0 = r0 * ASTR + c * 8;
                const int o8 = o0 + 8 * ASTR;
                uint4 Ah  = *(const uint4*)(sA_hi + o0);
                uint4 Ah8 = *(const uint4*)(sA_hi + o8);
                uint4 Al  = *(const uint4*)(sA_lo + o0);
                uint4 Al8 = *(const uint4*)(sA_lo + o8);
                uint32_t ah0[4] = {Ah.x, Ah8.x, Ah.y, Ah8.y};   // k16 chunk 0
                uint32_t ah1[4] = {Ah.z, Ah8.z, Ah.w, Ah8.w};   // k16 chunk 1
                uint32_t al0[4] = {Al.x, Al8.x, Al.y, Al8.y};
                uint32_t al1[4] = {Al.z, Al8.z, Al.w, Al8.w};
                #pragma unroll
                for (int j = 0; j < 4; ++j) {
                    const int ni = nh * 4 + j;
                    uint32_t bh0[2] = {Bh[j].x, Bh[j].y};
                    uint32_t bh1[2] = {Bh[j].z, Bh[j].w};
                    uint32_t bl0[2] = {Bl[j].x, Bl[j].y};
                    uint32_t bl1[2] = {Bl[j].z, Bl[j].w};
                    mma_bf16(acc[mi][ni], ah0, bh0);   // hi*hi
                    mma_bf16(acc[mi][ni], ah1, bh1);
                    mma_bf16(acc[mi][ni], ah0, bl0);   // hi*lo
                    mma_bf16(acc[mi][ni], ah1, bl1);
                    mma_bf16(acc[mi][ni], al0, bh0);   // lo*hi
                    mma_bf16(acc[mi][ni], al1, bh1);
                }
            }
        }
        st = st + 1 == 3 ? 0 : st + 1;
    }

    // Epilogue: c0=(g,2c) c1=(g,2c+1) c2=(g+8,2c) c3=(g+8,2c+1)
    #pragma unroll
    for (int mi = 0; mi < MT; ++mi) {
        const int r0 = brow + wm + mi * 16 + g;
        #pragma unroll
        for (int ni = 0; ni < NT; ++ni) {
            const int cc = bcol + wn + ni * 8 + 2 * c;
            *reinterpret_cast<float2*>(C + (size_t)r0 * N + cc) =
                make_float2(acc[mi][ni][0], acc[mi][ni][1]);
            *reinterpret_cast<float2*>(C + (size_t)(r0 + 8) * N + cc) =
                make_float2(acc[mi][ni][2], acc[mi][ni][3]);
        }
    }
}

// ---- split fp32 -> (hi,lo) bf16, k-permuted, pair-packed u32 --------------
// permuted pair index for even k: kk=k&31: c=(kk&7)>>1, p=((kk>>4)&1)*4+((kk>>3)&1)*2
// pair goes to u32 slot ( (k&~31) + c*8 + p ) / 2
__global__ void __launch_bounds__(256)
split_perm_k(const float4* __restrict__ in, uint32_t* __restrict__ hi,
             uint32_t* __restrict__ lo, int n4)
{
    for (int i = blockIdx.x * blockDim.x + threadIdx.x; i < n4; i += gridDim.x * blockDim.x) {
        float4 v = in[i];
        int e = i * 4;                         // k of v.x (mult of 4)
        int blk = e & ~31;
        #pragma unroll
        for (int pr = 0; pr < 2; ++pr) {
            float x = pr ? v.z : v.x;
            float y = pr ? v.w : v.y;
            int kk = (e & 31) + 2 * pr;
            int idx = (((kk & 7) >> 1) << 3) + (((kk >> 4) & 1) << 2) + (((kk >> 3) & 1) << 1);
            uint16_t hx = bf16_bits(x), hy = bf16_bits(y);
            float fx = __bfloat162float(*reinterpret_cast<__nv_bfloat16*>(&hx));
            float fy = __bfloat162float(*reinterpret_cast<__nv_bfloat16*>(&hy));
            uint16_t lx = bf16_bits(x - fx), ly = bf16_bits(y - fy);
            size_t pos = (size_t)(blk + idx) >> 1;
            pos += (size_t)(e >> 5) * 0;       // (blk already includes row offset via e)
            hi[((size_t)e & ~31ull) / 2 + (idx >> 1)] = (uint32_t)hx | ((uint32_t)hy << 16);
            lo[((size_t)e & ~31ull) / 2 + (idx >> 1)] = (uint32_t)lx | ((uint32_t)ly << 16);
            (void)pos;
        }
    }
}

// ---- conv + gating; emits y split (hi/lo) k-permuted pair-packed ----------
__global__ void __launch_bounds__(256)
conv_gate_kernel(const float* __restrict__ BCx, const float* __restrict__ w,
                 uint32_t* __restrict__ yhi, uint32_t* __restrict__ ylo)
{
    const int idx = blockIdx.x * blockDim.x + threadIdx.x;   // < 8192*2048
    const int h = idx & (HD - 1);
    const int m = idx >> 11;
    const int s = m & (SEQ - 1);

    const float* row = BCx + (size_t)m * NN1;
    const float w0 = w[h * 3 + 0];
    const float w1 = w[h * 3 + 1];
    const float w2 = w[h * 3 + 2];

    float acc = w2 * (row[h] * row[2 * HD + h]);
    if (s >= 1) { const float* r1 = row - NN1;     acc += w1 * (r1[h] * r1[2 * HD + h]); }
    if (s >= 2) { const float* r2 = row - 2 * NN1; acc += w0 * (r2[h] * r2[2 * HD + h]); }
    const float val = acc * row[HD + h];

    uint32_t hb = bf16_bits(val);
    float hf = __bfloat162float(*reinterpret_cast<__nv_bfloat16*>(&hb));
    uint32_t lb = bf16_bits(val - hf);

    // pair with neighbor h^1 (same warp: lane parity == h parity)
    uint32_t ohb = __shfl_xor_sync(0xFFFFFFFFu, hb, 1);
    uint32_t olb = __shfl_xor_sync(0xFFFFFFFFu, lb, 1);
    if ((h & 1) == 0) {
        int kk = h & 31;
        int pidx = (((kk & 7) >> 1) << 3) + (((kk >> 4) & 1) << 2) + (((kk >> 3) & 1) << 1);
        size_t pos = ((size_t)m * HD + (h & ~31)) / 2 + (pidx >> 1);
        yhi[pos] = hb | (ohb << 16);
        ylo[pos] = lb | (olb << 16);
    }
}

// ---------------------------------------------------------------------------
extern "C" void kernel_launch(void* const* d_in, const int* in_sizes, int n_in,
                              void* d_out, int out_size)
{
    const float* hs    = (const float*)d_in[0];
    const float* Win   = (const float*)d_in[1];
    const float* convw = (const float*)d_in[2];
    const float* Wout  = (const float*)d_in[3];
    float* out = (float*)d_out;

    uint32_t *hid_h, *hid_l, *win_h, *win_l, *wout_h, *wout_l, *y_h, *y_l;
    float* bcx;
    cudaGetSymbolAddress((void**)&hid_h,  g_hid_hi);
    cudaGetSymbolAddress((void**)&hid_l,  g_hid_lo);
    cudaGetSymbolAddress((void**)&win_h,  g_win_hi);
    cudaGetSymbolAddress((void**)&win_l,  g_win_lo);
    cudaGetSymbolAddress((void**)&wout_h, g_wout_hi);
    cudaGetSymbolAddress((void**)&wout_l, g_wout_lo);
    cudaGetSymbolAddress((void**)&y_h,    g_y_hi);
    cudaGetSymbolAddress((void**)&y_l,    g_y_lo);
    cudaGetSymbolAddress((void**)&bcx,    g_BCx);

    cudaFuncSetAttribute(gemm_bf16s_tn,
                         cudaFuncAttributeMaxDynamicSharedMemorySize, SMEM_BYTES);

    // split + permute GEMM operands
    split_perm_k<<<2048, 256>>>((const float4*)hs,   hid_h,  hid_l,  MTOT * KD / 4);
    split_perm_k<<<2048, 256>>>((const float4*)Win,  win_h,  win_l,  NN1  * KD / 4);
    split_perm_k<<<2048, 256>>>((const float4*)Wout, wout_h, wout_l, NN2  * KD / 4);

    // GEMM1: BCx = hidden @ W_in^T   [8192 x 6144]
    gemm_bf16s_tn<<<dim3(NN1 / BN, MTOT / BM), NTHREADS, SMEM_BYTES>>>(
        hid_h, hid_l, win_h, win_l, bcx, NN1, KD);

    // conv + gating -> y (split + permuted)
    conv_gate_kernel<<<(MTOT * HD) / 256, 256>>>(bcx, convw, y_h, y_l);

    // GEMM2: out = y @ W_out^T   [8192 x 2048]
    gemm_bf16s_tn<<<dim3(NN2 / BN, MTOT / BM), NTHREADS, SMEM_BYTES>>>(
        y_h, y_l, wout_h, wout_l, out, NN2, KD);
}

// round 8
// speedup vs baseline: 2.1709x; 2.1709x over previous
#include <cuda_runtime.h>
#include <cstdint>
#include <cstddef>

// ---------------------------------------------------------------------------
// Lfm2ShortConv (sm_103 legacy-tensor path).
//   BCx = hidden @ W_in^T        GEMM1  8192x6144x2048
//   y   = C * conv3(B*x)         fused elementwise
//   out = y @ W_out^T            GEMM2  8192x2048x2048
// R8 insight: prior rounds were cp.async ISSUE-bound (3072 x 16B LDGSTS per
// ktile per SM ~ 6k cyc >> 2k cyc HMMA). Fix: operands pre-stored TILE-MAJOR
// (contiguous 16KB/32KB tiles, tf32-rounded, k-permuted, XOR-swizzled) and
// loaded with cp.async.bulk (plain 1D, sm_90 baseline) + mbarrier: 2 bulk
// ops per ktile instead of 3072 cp.asyncs. MMA loop identical to round 5.
// ---------------------------------------------------------------------------

#define SEQ  4096
#define HD   2048
#define MTOT 8192
#define KD   2048
#define NN1  6144
#define NN2  2048

// Scratch (__device__ globals: allocation-free rule), tile-major images
__device__ float g_hidT [(size_t)MTOT * KD];   // A1: 128-row tiles
__device__ float g_winT [(size_t)NN1  * KD];   // B1: 256-row tiles
__device__ float g_woutT[(size_t)NN2  * KD];   // B2: 256-row tiles
__device__ float g_yT   [(size_t)MTOT * KD];   // A2: 128-row tiles
__device__ float g_BCx  [(size_t)MTOT * NN1];  // GEMM1 out, plain row-major

// ---- GEMM tiling ----------------------------------------------------------
constexpr int BM = 128, BN = 256, BK = 32;
constexpr int NTHREADS = 256;                  // 8 warps: 2 (M) x 4 (N)
constexpr int WM_ = 64, WN_ = 64;
constexpr int MT = WM_ / 16;                   // 4
constexpr int NT = WN_ / 8;                    // 8
constexpr int KTILES = KD / BK;                // 64
constexpr int NSTAGE = 4;
constexpr uint32_t A_TILE_B = BM * BK * 4;     // 16384
constexpr uint32_t B_TILE_B = BN * BK * 4;     // 32768
constexpr uint32_t STAGE_B  = A_TILE_B + B_TILE_B;       // 49152
constexpr uint32_t BARS_OFF = NSTAGE * STAGE_B;          // 196608
constexpr uint32_t SMEM_DYN = BARS_OFF + 64;

// ---- PTX helpers ----------------------------------------------------------
__device__ __forceinline__ uint32_t smem_u32(const void* p) {
    uint32_t a;
    asm("{ .reg .u64 t; cvta.to.shared.u64 t, %1; cvt.u32.u64 %0, t; }" : "=r"(a) : "l"(p));
    return a;
}
__device__ __forceinline__ uint32_t f2tf(float f) {
    uint32_t u; asm("cvt.rna.tf32.f32 %0, %1;" : "=r"(u) : "f"(f)); return u;
}
__device__ __forceinline__ void bulk_g2s(uint32_t dst, const void* src,
                                         uint32_t bytes, uint32_t bar) {
    asm volatile(
        "cp.async.bulk.shared::cluster.global.mbarrier::complete_tx::bytes "
        "[%0], [%1], %2, [%3];"
        :: "r"(dst), "l"(src), "r"(bytes), "r"(bar) : "memory");
}
#define MBAR_INIT(a, c) \
    asm volatile("mbarrier.init.shared.b64 [%0], %1;" :: "r"(a), "r"(c) : "memory")
#define MBAR_EXPECT_TX(a, b) \
    asm volatile("mbarrier.arrive.expect_tx.shared.b64 _, [%0], %1;" :: "r"(a), "r"(b) : "memory")
#define FENCE_PROXY_ASYNC() asm volatile("fence.proxy.async.shared::cta;" ::: "memory")
#define MBAR_WAIT(mbar, parity) do {                                          \
    uint32_t _m = (uint32_t)(mbar); uint32_t _p = (uint32_t)(parity);         \
    asm volatile(                                                             \
        "{\n\t.reg .pred P1;\n\t"                                             \
        "WL_%=:\n\t"                                                          \
        "mbarrier.try_wait.parity.acquire.cta.shared::cta.b64 P1, [%0], %1, 0x989680;\n\t" \
        "@P1 bra.uni WD_%=;\n\t"                                              \
        "bra.uni WL_%=;\n\t"                                                  \
        "WD_%=:\n\t}"                                                         \
        :: "r"(_m), "r"(_p) : "memory");                                      \
} while (0)

__device__ __forceinline__ void mma_tf32(float* c, const uint32_t* a, const uint32_t* b) {
    asm volatile(
        "mma.sync.aligned.m16n8k8.row.col.f32.tf32.tf32.f32 "
        "{%0,%1,%2,%3}, {%4,%5,%6,%7}, {%8,%9}, {%0,%1,%2,%3};\n"
        : "+f"(c[0]), "+f"(c[1]), "+f"(c[2]), "+f"(c[3])
        : "r"(a[0]), "r"(a[1]), "r"(a[2]), "r"(a[3]), "r"(b[0]), "r"(b[1]));
}

// ---- TN GEMM: C[M,N] = A[M,K] * B[N,K]^T, tile-major bulk-fed operands ----
__global__ void __launch_bounds__(NTHREADS, 1)
gemm_bulk(const float* __restrict__ At, const float* __restrict__ Bt,
          float* __restrict__ C, int N)
{
    extern __shared__ char smc[];
    float* smf = (float*)smc;
    const uint32_t base = smem_u32(smc);

    const int tid  = threadIdx.x;
    const int lane = tid & 31;
    const int warp = tid >> 5;
    const int wm = (warp >> 2) * WM_;          // 0 or 64
    const int wn = (warp & 3)  * WN_;          // 0,64,128,192
    const int g  = lane >> 2;                  // 0..7
    const int c  = lane & 3;                   // 0..3

    if (tid == 0) {
        #pragma unroll
        for (int s = 0; s < NSTAGE; s++) MBAR_INIT(base + BARS_OFF + 8 * s, 1u);
        FENCE_PROXY_ASYNC();
    }
    __syncthreads();

    const float* Abase = At + ((size_t)blockIdx.y * KTILES) * (BM * BK);
    const float* Bbase = Bt + ((size_t)blockIdx.x * KTILES) * (BN * BK);

    auto fill = [&](int kt) {
        const int s = kt & 3;
        const uint32_t sb  = base + (uint32_t)s * STAGE_B;
        const uint32_t bar = base + BARS_OFF + 8 * s;
        MBAR_EXPECT_TX(bar, STAGE_B);
        bulk_g2s(sb,            Abase + (size_t)kt * (BM * BK), A_TILE_B, bar);
        bulk_g2s(sb + A_TILE_B, Bbase + (size_t)kt * (BN * BK), B_TILE_B, bar);
    };

    if (tid == 0) { fill(0); fill(1); fill(2); }

    float acc[MT][NT][4];
    #pragma unroll
    for (int i = 0; i < MT; i++)
        #pragma unroll
        for (int j = 0; j < NT; j++)
            #pragma unroll
            for (int q = 0; q < 4; q++) acc[i][j][q] = 0.f;

    for (int kt = 0; kt < KTILES; ++kt) {
        const int st = kt & 3;
        MBAR_WAIT(base + BARS_OFF + 8 * st, (kt >> 2) & 1);

        const float* as = smf + st * (STAGE_B / 4);
        const float* bs = as + (A_TILE_B / 4);

        // stored layout per tile row: 32 floats = 8 x 16B atoms; atom for
        // (c,h) is (2c+h) ^ (row&7); floats map k = 16h + 4j + c (j=0..3)
        #pragma unroll
        for (int h = 0; h < 2; ++h) {
            const int at = 2 * c + h;
            float4 bf[NT];
            #pragma unroll
            for (int ni = 0; ni < NT; ++ni) {
                const int r = wn + ni * 8 + g;
                bf[ni] = *(const float4*)(bs + r * 32 + ((at ^ g) << 2));
            }
            #pragma unroll
            for (int mi = 0; mi < MT; ++mi) {
                const int r0 = wm + mi * 16 + g;
                float4 a_lo = *(const float4*)(as + r0 * 32 + ((at ^ g) << 2));
                float4 a_hi = *(const float4*)(as + (r0 + 8) * 32 + ((at ^ g) << 2));
                const float* alo = &a_lo.x;
                const float* ahi = &a_hi.x;
                #pragma unroll
                for (int k2 = 0; k2 < 2; ++k2) {
                    uint32_t af[4];
                    af[0] = __float_as_uint(alo[2 * k2 + 0]);
                    af[1] = __float_as_uint(ahi[2 * k2 + 0]);
                    af[2] = __float_as_uint(alo[2 * k2 + 1]);
                    af[3] = __float_as_uint(ahi[2 * k2 + 1]);
                    #pragma unroll
                    for (int ni = 0; ni < NT; ++ni) {
                        const float* bp = &bf[ni].x;
                        uint32_t bfr[2];
                        bfr[0] = __float_as_uint(bp[2 * k2 + 0]);
                        bfr[1] = __float_as_uint(bp[2 * k2 + 1]);
                        mma_tf32(acc[mi][ni], af, bfr);
                    }
                }
            }
        }
        __syncthreads();                        // stage consumed by all warps
        if (tid == 0 && kt + 3 < KTILES) fill(kt + 3);
    }

    // Epilogue: c0=(g,2c) c1=(g,2c+1) c2=(g+8,2c) c3=(g+8,2c+1)
    const int brow = blockIdx.y * BM;
    const int bcol = blockIdx.x * BN;
    #pragma unroll
    for (int mi = 0; mi < MT; ++mi) {
        const int r0 = brow + wm + mi * 16 + g;
        #pragma unroll
        for (int ni = 0; ni < NT; ++ni) {
            const int cc = bcol + wn + ni * 8 + 2 * c;
            *reinterpret_cast<float2*>(C + (size_t)r0 * N + cc) =
                make_float2(acc[mi][ni][0], acc[mi][ni][1]);
            *reinterpret_cast<float2*>(C + (size_t)(r0 + 8) * N + cc) =
                make_float2(acc[mi][ni][2], acc[mi][ni][3]);
        }
    }
}

// ---- prep: fp32 [R,2048] -> tf32-rounded tile-major (TH rows/tile) --------
// element (r,k): tile (r/TH, k/32); within: rr=r%TH, kk=k&31,
// pos p=(kk&3)*8+(kk>>2); atom=(p>>2)^(rr&7); slot = rr*32 + atom*4 + (p&3)
__global__ void __launch_bounds__(256)
prep_tiles(const float4* __restrict__ in, float* __restrict__ out, int n4, int TH)
{
    for (int i = blockIdx.x * blockDim.x + threadIdx.x; i < n4; i += gridDim.x * blockDim.x) {
        float4 v = in[i];
        const int e = i * 4;
        const int r = e >> 11;
        const int k = e & 2047;
        const int rr = r % TH;
        const int q  = (k & 31) >> 2;          // kk>>2, kk%4==0
        float* tb = out + ((size_t)(r / TH) * KTILES + (k >> 5)) * ((size_t)TH * 32)
                  + rr * 32;
        const int sw = rr & 7;
        const int qa = q >> 2, qb = q & 3;
        tb[(((0 + qa) ^ sw) << 2) + qb] = __uint_as_float(f2tf(v.x));
        tb[(((2 + qa) ^ sw) << 2) + qb] = __uint_as_float(f2tf(v.y));
        tb[(((4 + qa) ^ sw) << 2) + qb] = __uint_as_float(f2tf(v.z));
        tb[(((6 + qa) ^ sw) << 2) + qb] = __uint_as_float(f2tf(v.w));
    }
}

// ---- conv + gating; emits y tf32-rounded into 128-row tile-major ----------
__global__ void __launch_bounds__(256)
conv_gate_kernel(const float* __restrict__ BCx, const float* __restrict__ w,
                 float* __restrict__ yT)
{
    const int idx = blockIdx.x * blockDim.x + threadIdx.x;   // < 8192*2048
    const int h = idx & (HD - 1);
    const int m = idx >> 11;
    const int s = m & (SEQ - 1);

    const float* row = BCx + (size_t)m * NN1;
    const float w0 = w[h * 3 + 0];
    const float w1 = w[h * 3 + 1];
    const float w2 = w[h * 3 + 2];

    float acc = w2 * (row[h] * row[2 * HD + h]);
    if (s >= 1) { const float* r1 = row - NN1;     acc += w1 * (r1[h] * r1[2 * HD + h]); }
    if (s >= 2) { const float* r2 = row - 2 * NN1; acc += w0 * (r2[h] * r2[2 * HD + h]); }
    const float val = acc * row[HD + h];

    const int rr = m & 127;
    const int kk = h & 31;
    const int p  = ((kk & 3) << 3) + (kk >> 2);
    const int atom = ((p >> 2) ^ (rr & 7));
    yT[((size_t)(m >> 7) * KTILES + (h >> 5)) * (128 * 32)
       + rr * 32 + (atom << 2) + (p & 3)] = __uint_as_float(f2tf(val));
}

// ---------------------------------------------------------------------------
extern "C" void kernel_launch(void* const* d_in, const int* in_sizes, int n_in,
                              void* d_out, int out_size)
{
    const float* hs    = (const float*)d_in[0];   // [2,4096,2048]
    const float* Win   = (const float*)d_in[1];   // [6144,2048]
    const float* convw = (const float*)d_in[2];   // [2048,1,3]
    const float* Wout  = (const float*)d_in[3];   // [2048,2048]
    float* out = (float*)d_out;

    float *hidT, *winT, *woutT, *yT, *bcx;
    cudaGetSymbolAddress((void**)&hidT,  g_hidT);
    cudaGetSymbolAddress((void**)&winT,  g_winT);
    cudaGetSymbolAddress((void**)&woutT, g_woutT);
    cudaGetSymbolAddress((void**)&yT,    g_yT);
    cudaGetSymbolAddress((void**)&bcx,   g_BCx);

    cudaFuncSetAttribute(gemm_bulk,
                         cudaFuncAttributeMaxDynamicSharedMemorySize, SMEM_DYN);

    // prep: round to tf32 + tile-major/permuted/swizzled images
    prep_tiles<<<2048, 256>>>((const float4*)hs,   hidT,  MTOT * KD / 4, 128);
    prep_tiles<<<2048, 256>>>((const float4*)Win,  winT,  NN1  * KD / 4, 256);
    prep_tiles<<<2048, 256>>>((const float4*)Wout, woutT, NN2  * KD / 4, 256);

    // GEMM1: BCx = hidden @ W_in^T   [8192 x 6144]
    gemm_bulk<<<dim3(NN1 / BN, MTOT / BM), NTHREADS, SMEM_DYN>>>(hidT, winT, bcx, NN1);

    // conv + gating -> yT (tile-major)
    conv_gate_kernel<<<(MTOT * HD) / 256, 256>>>(bcx, convw, yT);

    // GEMM2: out = y @ W_out^T   [8192 x 2048]
    gemm_bulk<<<dim3(NN2 / BN, MTOT / BM), NTHREADS, SMEM_DYN>>>(yT, woutT, out, NN2);
}

// round 9
// speedup vs baseline: 2.3075x; 1.0629x over previous
#include <cuda_runtime.h>
#include <cstdint>
#include <cstddef>

// ---------------------------------------------------------------------------
// Lfm2ShortConv (sm_103 legacy-tensor path).
//   BCx = hidden @ W_in^T        GEMM1  8192x6144x2048
//   y   = C * conv3(B*x)         fused elementwise
//   out = y @ W_out^T            GEMM2  8192x2048x2048
// R8: tile-major operands + cp.async.bulk feed (2 bulk ops/ktile) -> 1548us.
// R9: kill per-ktile __syncthreads lockstep. full[s] (tx mbarrier) +
// empty[s] (arrive-count 8, one arrive per warp after consuming) lets warps
// skew up to pipeline depth; producer thread refills once all warps arrive.
// ---------------------------------------------------------------------------

#define SEQ  4096
#define HD   2048
#define MTOT 8192
#define KD   2048
#define NN1  6144
#define NN2  2048

// Scratch (__device__ globals: allocation-free rule), tile-major images
__device__ float g_hidT [(size_t)MTOT * KD];   // A1: 128-row tiles
__device__ float g_winT [(size_t)NN1  * KD];   // B1: 256-row tiles
__device__ float g_woutT[(size_t)NN2  * KD];   // B2: 256-row tiles
__device__ float g_yT   [(size_t)MTOT * KD];   // A2: 128-row tiles
__device__ float g_BCx  [(size_t)MTOT * NN1];  // GEMM1 out, plain row-major

// ---- GEMM tiling ----------------------------------------------------------
constexpr int BM = 128, BN = 256, BK = 32;
constexpr int NTHREADS = 256;                  // 8 warps: 2 (M) x 4 (N)
constexpr int WM_ = 64, WN_ = 64;
constexpr int MT = WM_ / 16;                   // 4
constexpr int NT = WN_ / 8;                    // 8
constexpr int KTILES = KD / BK;                // 64
constexpr int NSTAGE = 4;
constexpr uint32_t A_TILE_B = BM * BK * 4;     // 16384
constexpr uint32_t B_TILE_B = BN * BK * 4;     // 32768
constexpr uint32_t STAGE_B  = A_TILE_B + B_TILE_B;       // 49152
constexpr uint32_t BARS_OFF = NSTAGE * STAGE_B;          // 196608
constexpr uint32_t SMEM_DYN = BARS_OFF + 16 * NSTAGE;    // full[4] + empty[4]

// ---- PTX helpers ----------------------------------------------------------
__device__ __forceinline__ uint32_t smem_u32(const void* p) {
    uint32_t a;
    asm("{ .reg .u64 t; cvta.to.shared.u64 t, %1; cvt.u32.u64 %0, t; }" : "=r"(a) : "l"(p));
    return a;
}
__device__ __forceinline__ uint32_t f2tf(float f) {
    uint32_t u; asm("cvt.rna.tf32.f32 %0, %1;" : "=r"(u) : "f"(f)); return u;
}
__device__ __forceinline__ void bulk_g2s(uint32_t dst, const void* src,
                                         uint32_t bytes, uint32_t bar) {
    asm volatile(
        "cp.async.bulk.shared::cluster.global.mbarrier::complete_tx::bytes "
        "[%0], [%1], %2, [%3];"
        :: "r"(dst), "l"(src), "r"(bytes), "r"(bar) : "memory");
}
#define MBAR_INIT(a, c) \
    asm volatile("mbarrier.init.shared.b64 [%0], %1;" :: "r"(a), "r"(c) : "memory")
#define MBAR_EXPECT_TX(a, b) \
    asm volatile("mbarrier.arrive.expect_tx.shared.b64 _, [%0], %1;" :: "r"(a), "r"(b) : "memory")
#define MBAR_ARRIVE(a) \
    asm volatile("mbarrier.arrive.release.cta.shared.b64 _, [%0];" :: "r"(a) : "memory")
#define FENCE_PROXY_ASYNC() asm volatile("fence.proxy.async.shared::cta;" ::: "memory")
#define MBAR_WAIT(mbar, parity) do {                                          \
    uint32_t _m = (uint32_t)(mbar); uint32_t _p = (uint32_t)(parity);         \
    asm volatile(                                                             \
        "{\n\t.reg .pred P1;\n\t"                                             \
        "WL_%=:\n\t"                                                          \
        "mbarrier.try_wait.parity.acquire.cta.shared::cta.b64 P1, [%0], %1, 0x989680;\n\t" \
        "@P1 bra.uni WD_%=;\n\t"                                              \
        "bra.uni WL_%=;\n\t"                                                  \
        "WD_%=:\n\t}"                                                         \
        :: "r"(_m), "r"(_p) : "memory");                                      \
} while (0)

__device__ __forceinline__ void mma_tf32(float* c, const uint32_t* a, const uint32_t* b) {
    asm volatile(
        "mma.sync.aligned.m16n8k8.row.col.f32.tf32.tf32.f32 "
        "{%0,%1,%2,%3}, {%4,%5,%6,%7}, {%8,%9}, {%0,%1,%2,%3};\n"
        : "+f"(c[0]), "+f"(c[1]), "+f"(c[2]), "+f"(c[3])
        : "r"(a[0]), "r"(a[1]), "r"(a[2]), "r"(a[3]), "r"(b[0]), "r"(b[1]));
}

// ---- TN GEMM: C[M,N] = A[M,K] * B[N,K]^T, tile-major bulk-fed operands ----
__global__ void __launch_bounds__(NTHREADS, 1)
gemm_bulk(const float* __restrict__ At, const float* __restrict__ Bt,
          float* __restrict__ C, int N)
{
    extern __shared__ char smc[];
    float* smf = (float*)smc;
    const uint32_t base = smem_u32(smc);
    const uint32_t fullb = base + BARS_OFF;          // full[s] at +8s
    const uint32_t emptb = fullb + 8 * NSTAGE;       // empty[s] at +8s

    const int tid  = threadIdx.x;
    const int lane = tid & 31;
    const int warp = tid >> 5;
    const int wm = (warp >> 2) * WM_;          // 0 or 64
    const int wn = (warp & 3)  * WN_;          // 0,64,128,192
    const int g  = lane >> 2;                  // 0..7
    const int c  = lane & 3;                   // 0..3

    if (tid == 0) {
        #pragma unroll
        for (int s = 0; s < NSTAGE; s++) {
            MBAR_INIT(fullb + 8 * s, 1u);
            MBAR_INIT(emptb + 8 * s, 8u);      // one arrive per warp
        }
        FENCE_PROXY_ASYNC();
    }
    __syncthreads();

    const float* Abase = At + ((size_t)blockIdx.y * KTILES) * (BM * BK);
    const float* Bbase = Bt + ((size_t)blockIdx.x * KTILES) * (BN * BK);

    auto fill = [&](int kt) {
        const int s = kt & 3;
        const uint32_t sb  = base + (uint32_t)s * STAGE_B;
        const uint32_t bar = fullb + 8 * s;
        MBAR_EXPECT_TX(bar, STAGE_B);
        bulk_g2s(sb,            Abase + (size_t)kt * (BM * BK), A_TILE_B, bar);
        bulk_g2s(sb + A_TILE_B, Bbase + (size_t)kt * (BN * BK), B_TILE_B, bar);
    };

    if (tid == 0) { fill(0); fill(1); fill(2); }

    float acc[MT][NT][4];
    #pragma unroll
    for (int i = 0; i < MT; i++)
        #pragma unroll
        for (int j = 0; j < NT; j++)
            #pragma unroll
            for (int q = 0; q < 4; q++) acc[i][j][q] = 0.f;

    for (int kt = 0; kt < KTILES; ++kt) {
        const int st = kt & 3;
        MBAR_WAIT(fullb + 8 * st, (kt >> 2) & 1);

        const float* as = smf + st * (STAGE_B / 4);
        const float* bs = as + (A_TILE_B / 4);

        // stored layout per tile row: 32 floats = 8 x 16B atoms; atom for
        // (c,h) is (2c+h) ^ (row&7); floats map k = 16h + 4j + c (j=0..3)
        #pragma unroll
        for (int h = 0; h < 2; ++h) {
            const int at = 2 * c + h;
            float4 bf[NT];
            #pragma unroll
            for (int ni = 0; ni < NT; ++ni) {
                const int r = wn + ni * 8 + g;
                bf[ni] = *(const float4*)(bs + r * 32 + ((at ^ g) << 2));
            }
            #pragma unroll
            for (int mi = 0; mi < MT; ++mi) {
                const int r0 = wm + mi * 16 + g;
                float4 a_lo = *(const float4*)(as + r0 * 32 + ((at ^ g) << 2));
                float4 a_hi = *(const float4*)(as + (r0 + 8) * 32 + ((at ^ g) << 2));
                const float* alo = &a_lo.x;
                const float* ahi = &a_hi.x;
                #pragma unroll
                for (int k2 = 0; k2 < 2; ++k2) {
                    uint32_t af[4];
                    af[0] = __float_as_uint(alo[2 * k2 + 0]);
                    af[1] = __float_as_uint(ahi[2 * k2 + 0]);
                    af[2] = __float_as_uint(alo[2 * k2 + 1]);
                    af[3] = __float_as_uint(ahi[2 * k2 + 1]);
                    #pragma unroll
                    for (int ni = 0; ni < NT; ++ni) {
                        const float* bp = &bf[ni].x;
                        uint32_t bfr[2];
                        bfr[0] = __float_as_uint(bp[2 * k2 + 0]);
                        bfr[1] = __float_as_uint(bp[2 * k2 + 1]);
                        mma_tf32(acc[mi][ni], af, bfr);
                    }
                }
            }
        }

        // this warp done with stage st (all its LDS issued; LDS completion
        // ordered before arrive by release semantics)
        if (lane == 0) MBAR_ARRIVE(emptb + 8 * st);

        // producer: refill stage (kt+3) once all 8 warps drained it
        if (tid == 0 && kt + 3 < KTILES) {
            const int fk = kt + 3;
            const int fs = fk & 3;
            if (fk >= NSTAGE)
                MBAR_WAIT(emptb + 8 * fs, ((fk >> 2) + 1) & 1);
            fill(fk);
        }
    }

    // Epilogue: c0=(g,2c) c1=(g,2c+1) c2=(g+8,2c) c3=(g+8,2c+1)
    const int brow = blockIdx.y * BM;
    const int bcol = blockIdx.x * BN;
    #pragma unroll
    for (int mi = 0; mi < MT; ++mi) {
        const int r0 = brow + wm + mi * 16 + g;
        #pragma unroll
        for (int ni = 0; ni < NT; ++ni) {
            const int cc = bcol + wn + ni * 8 + 2 * c;
            *reinterpret_cast<float2*>(C + (size_t)r0 * N + cc) =
                make_float2(acc[mi][ni][0], acc[mi][ni][1]);
            *reinterpret_cast<float2*>(C + (size_t)(r0 + 8) * N + cc) =
                make_float2(acc[mi][ni][2], acc[mi][ni][3]);
        }
    }
}

// ---- prep: fp32 [R,2048] -> tf32-rounded tile-major (TH rows/tile) --------
// element (r,k): tile (r/TH, k/32); within: rr=r%TH, kk=k&31,
// pos p=(kk&3)*8+(kk>>2); atom=(p>>2)^(rr&7); slot = rr*32 + atom*4 + (p&3)
__global__ void __launch_bounds__(256)
prep_tiles(const float4* __restrict__ in, float* __restrict__ out, int n4, int TH)
{
    for (int i = blockIdx.x * blockDim.x + threadIdx.x; i < n4; i += gridDim.x * blockDim.x) {
        float4 v = in[i];
        const int e = i * 4;
        const int r = e >> 11;
        const int k = e & 2047;
        const int rr = r % TH;
        const int q  = (k & 31) >> 2;
        float* tb = out + ((size_t)(r / TH) * KTILES + (k >> 5)) * ((size_t)TH * 32)
                  + rr * 32;
        const int sw = rr & 7;
        const int qa = q >> 2, qb = q & 3;
        tb[(((0 + qa) ^ sw) << 2) + qb] = __uint_as_float(f2tf(v.x));
        tb[(((2 + qa) ^ sw) << 2) + qb] = __uint_as_float(f2tf(v.y));
        tb[(((4 + qa) ^ sw) << 2) + qb] = __uint_as_float(f2tf(v.z));
        tb[(((6 + qa) ^ sw) << 2) + qb] = __uint_as_float(f2tf(v.w));
    }
}

// ---- conv + gating; emits y tf32-rounded into 128-row tile-major ----------
__global__ void __launch_bounds__(256)
conv_gate_kernel(const float* __restrict__ BCx, const float* __restrict__ w,
                 float* __restrict__ yT)
{
    const int idx = blockIdx.x * blockDim.x + threadIdx.x;   // < 8192*2048
    const int h = idx & (HD - 1);
    const int m = idx >> 11;
    const int s = m & (SEQ - 1);

    const float* row = BCx + (size_t)m * NN1;
    const float w0 = w[h * 3 + 0];
    const float w1 = w[h * 3 + 1];
    const float w2 = w[h * 3 + 2];

    float acc = w2 * (row[h] * row[2 * HD + h]);
    if (s >= 1) { const float* r1 = row - NN1;     acc += w1 * (r1[h] * r1[2 * HD + h]); }
    if (s >= 2) { const float* r2 = row - 2 * NN1; acc += w0 * (r2[h] * r2[2 * HD + h]); }
    const float val = acc * row[HD + h];

    const int rr = m & 127;
    const int kk = h & 31;
    const int p  = ((kk & 3) << 3) + (kk >> 2);
    const int atom = ((p >> 2) ^ (rr & 7));
    yT[((size_t)(m >> 7) * KTILES + (h >> 5)) * (128 * 32)
       + rr * 32 + (atom << 2) + (p & 3)] = __uint_as_float(f2tf(val));
}

// ---------------------------------------------------------------------------
extern "C" void kernel_launch(void* const* d_in, const int* in_sizes, int n_in,
                              void* d_out, int out_size)
{
    const float* hs    = (const float*)d_in[0];   // [2,4096,2048]
    const float* Win   = (const float*)d_in[1];   // [6144,2048]
    const float* convw = (const float*)d_in[2];   // [2048,1,3]
    const float* Wout  = (const float*)d_in[3];   // [2048,2048]
    float* out = (float*)d_out;

    float *hidT, *winT, *woutT, *yT, *bcx;
    cudaGetSymbolAddress((void**)&hidT,  g_hidT);
    cudaGetSymbolAddress((void**)&winT,  g_winT);
    cudaGetSymbolAddress((void**)&woutT, g_woutT);
    cudaGetSymbolAddress((void**)&yT,    g_yT);
    cudaGetSymbolAddress((void**)&bcx,   g_BCx);

    cudaFuncSetAttribute(gemm_bulk,
                         cudaFuncAttributeMaxDynamicSharedMemorySize, SMEM_DYN);

    // prep: round to tf32 + tile-major/permuted/swizzled images
    prep_tiles<<<2048, 256>>>((const float4*)hs,   hidT,  MTOT * KD / 4, 128);
    prep_tiles<<<2048, 256>>>((const float4*)Win,  winT,  NN1  * KD / 4, 256);
    prep_tiles<<<2048, 256>>>((const float4*)Wout, woutT, NN2  * KD / 4, 256);

    // GEMM1: BCx = hidden @ W_in^T   [8192 x 6144]
    gemm_bulk<<<dim3(NN1 / BN, MTOT / BM), NTHREADS, SMEM_DYN>>>(hidT, winT, bcx, NN1);

    // conv + gating -> yT (tile-major)
    conv_gate_kernel<<<(MTOT * HD) / 256, 256>>>(bcx, convw, yT);

    // GEMM2: out = y @ W_out^T   [8192 x 2048]
    gemm_bulk<<<dim3(NN2 / BN, MTOT / BM), NTHREADS, SMEM_DYN>>>(yT, woutT, out, NN2);
}